// round 1
// baseline (speedup 1.0000x reference)
#include <cuda_runtime.h>
#include <math.h>

// ---------------- problem constants ----------------
#define BB      8
#define TT      4
#define NPTS    1024
#define MPTS    4096
#define CIN     256
#define CORIG   128
#define CCAT    384
#define P1      256
#define P2      256
#define FRAMES  32          // B*T
#define EPS_D   1e-8f
#define EPS_BN  1e-5f

// ---------------- scratch (device globals, no runtime alloc) ----------------
__device__ int   g_idx[FRAMES * MPTS * 3];
__device__ float g_w  [FRAMES * MPTS * 3];
__device__ float g_featT[(size_t)FRAMES * NPTS * CIN];    // [f][n][c]   32 MB
__device__ float g_origT[(size_t)FRAMES * MPTS * CORIG];  // [f][m][c]   64 MB
__device__ float g_ZT   [(size_t)FRAMES * NPTS * P1];     // [f][n][o]   32 MB
__device__ float g_y1   [(size_t)FRAMES * MPTS * P1];     // [f][m][o]  128 MB
__device__ float g_y2   [(size_t)FRAMES * MPTS * P2];     // [f][m][o]  128 MB
__device__ float g_W1aT[CIN * P1];    // [c][o]
__device__ float g_W1bT[CORIG * P1];  // [c][o]
__device__ float g_W2T [P1 * P2];     // [c][o]
__device__ float g_sum1[TT * P1], g_sq1[TT * P1], g_a1[TT * P1], g_b1[TT * P1];
__device__ float g_sum2[TT * P2], g_sq2[TT * P2], g_a2[TT * P2], g_b2[TT * P2];

// ---------------- prep: zero stats, transpose weights ----------------
__global__ void prep_kernel(const float* __restrict__ W1, const float* __restrict__ W2) {
    int i = blockIdx.x * 256 + threadIdx.x;
    if (i < TT * P1) { g_sum1[i] = 0.f; g_sq1[i] = 0.f; g_sum2[i] = 0.f; g_sq2[i] = 0.f; }
    if (i < P1 * CCAT) {
        int o = i / CCAT, c = i % CCAT;
        float v = W1[i];
        if (c < CIN) g_W1aT[c * P1 + o] = v;
        else         g_W1bT[(c - CIN) * P1 + o] = v;
    }
    if (i < P2 * P1) {
        int o = i / P1, c = i % P1;
        g_W2T[c * P2 + o] = W2[i];
    }
}

// ---------------- three_nn: per (frame, m) top-3 nearest + weights ----------------
__global__ void knn_kernel(const float* __restrict__ xyzs, const float* __restrict__ oxyzs) {
    __shared__ float sx[NPTS], sy[NPTS], sz[NPTS];
    int f = blockIdx.y;
    const float* p = xyzs + (size_t)f * NPTS * 3;
    for (int i = threadIdx.x; i < NPTS; i += 256) {
        sx[i] = p[3 * i]; sy[i] = p[3 * i + 1]; sz[i] = p[3 * i + 2];
    }
    __syncthreads();

    int m = blockIdx.x * 256 + threadIdx.x;
    const float* q = oxyzs + ((size_t)f * MPTS + m) * 3;
    float qx = q[0], qy = q[1], qz = q[2];

    float b0 = 1e30f, b1 = 1e30f, b2 = 1e30f;
    int   i0 = 0,     i1 = 0,     i2 = 0;
    #pragma unroll 4
    for (int n = 0; n < NPTS; n++) {
        float dx = qx - sx[n], dy = qy - sy[n], dz = qz - sz[n];
        float d = fmaf(dx, dx, fmaf(dy, dy, dz * dz));
        if (d < b2) {
            if (d < b1) {
                b2 = b1; i2 = i1;
                if (d < b0) { b1 = b0; i1 = i0; b0 = d; i0 = n; }
                else        { b1 = d;  i1 = n; }
            } else { b2 = d; i2 = n; }
        }
    }
    float w0 = 1.f / (b0 + EPS_D), w1 = 1.f / (b1 + EPS_D), w2 = 1.f / (b2 + EPS_D);
    float inv = 1.f / (w0 + w1 + w2);
    size_t base = ((size_t)f * MPTS + m) * 3;
    g_idx[base] = i0; g_idx[base + 1] = i1; g_idx[base + 2] = i2;
    g_w[base] = w0 * inv; g_w[base + 1] = w1 * inv; g_w[base + 2] = w2 * inv;
}

// ---------------- tiled transpose  in[f][R][Cc] -> out[f][Cc][R] ----------------
__global__ void transpose_kernel(const float* __restrict__ in, int R, int Cc, int which) {
    __shared__ float tile[32][33];
    float* outg = which ? g_origT : g_featT;
    int f = blockIdx.z;
    const float* A = in   + (size_t)f * R * Cc;
    float*       O = outg + (size_t)f * R * Cc;
    int c0 = blockIdx.x * 32, r0 = blockIdx.y * 32;
    int tx = threadIdx.x, ty = threadIdx.y;            // 32 x 8
    #pragma unroll
    for (int i = ty; i < 32; i += 8)
        tile[i][tx] = A[(size_t)(r0 + i) * Cc + c0 + tx];
    __syncthreads();
    #pragma unroll
    for (int i = ty; i < 32; i += 8)
        O[(size_t)(c0 + i) * R + r0 + tx] = tile[tx][i];
}

// ---------------- SGEMM 128x128x8, 8x8/thread, row-major C=A@B ----------------
// A: [f][M][K], B: [K][N] (shared weights), C: [f][M][N]
// TRANS: A element -> relu(scale[t][k]*x + bias[t][k]) (fused BN1+ReLU)
template <int M, int N, int K, bool TRANS>
__device__ __forceinline__ void sgemm_body(const float* __restrict__ Aall,
                                           const float* __restrict__ B,
                                           float* __restrict__ Call,
                                           const float* __restrict__ scl,
                                           const float* __restrict__ bia) {
    __shared__ float As[8][128];
    __shared__ float Bs[8][128];
    __shared__ float s_sc[256], s_bi[256];

    int f = blockIdx.z, t = f & 3;
    const float* A = Aall + (size_t)f * M * K;
    float*       C = Call + (size_t)f * M * N;
    int tid = threadIdx.x;

    if (TRANS) {
        for (int i = tid; i < K; i += 256) {
            s_sc[i] = scl[t * 256 + i];
            s_bi[i] = bia[t * 256 + i];
        }
    }
    __syncthreads();

    int bm = blockIdx.y * 128, bn = blockIdx.x * 128;
    int arow = tid >> 1, acol = (tid & 1) * 4;
    int brow = tid >> 5, bcol = (tid & 31) * 4;
    int tm = (tid >> 4) * 8, tn = (tid & 15) * 8;

    float acc[8][8];
    #pragma unroll
    for (int i = 0; i < 8; i++)
        #pragma unroll
        for (int j = 0; j < 8; j++) acc[i][j] = 0.f;

    const float* Aptr = A + (size_t)(bm + arow) * K + acol;
    const float* Bptr = B + (size_t)brow * N + bn + bcol;

    for (int k0 = 0; k0 < K; k0 += 8) {
        float4 av = *(const float4*)(Aptr + k0);
        float4 bv = *(const float4*)(Bptr + (size_t)k0 * N);
        if (TRANS) {
            int c = k0 + acol;
            av.x = fmaxf(0.f, fmaf(s_sc[c + 0], av.x, s_bi[c + 0]));
            av.y = fmaxf(0.f, fmaf(s_sc[c + 1], av.y, s_bi[c + 1]));
            av.z = fmaxf(0.f, fmaf(s_sc[c + 2], av.z, s_bi[c + 2]));
            av.w = fmaxf(0.f, fmaf(s_sc[c + 3], av.w, s_bi[c + 3]));
        }
        __syncthreads();
        As[acol + 0][arow] = av.x;
        As[acol + 1][arow] = av.y;
        As[acol + 2][arow] = av.z;
        As[acol + 3][arow] = av.w;
        *(float4*)&Bs[brow][bcol] = bv;
        __syncthreads();

        #pragma unroll
        for (int kk = 0; kk < 8; kk++) {
            float af[8], bf[8];
            #pragma unroll
            for (int i = 0; i < 8; i++) af[i] = As[kk][tm + i];
            #pragma unroll
            for (int j = 0; j < 8; j++) bf[j] = Bs[kk][tn + j];
            #pragma unroll
            for (int i = 0; i < 8; i++)
                #pragma unroll
                for (int j = 0; j < 8; j++)
                    acc[i][j] = fmaf(af[i], bf[j], acc[i][j]);
        }
    }

    #pragma unroll
    for (int i = 0; i < 8; i++) {
        float4 v0 = make_float4(acc[i][0], acc[i][1], acc[i][2], acc[i][3]);
        float4 v1 = make_float4(acc[i][4], acc[i][5], acc[i][6], acc[i][7]);
        *(float4*)&C[(size_t)(bm + tm + i) * N + bn + tn]     = v0;
        *(float4*)&C[(size_t)(bm + tm + i) * N + bn + tn + 4] = v1;
    }
}

__global__ void __launch_bounds__(256) gemmZ_kernel() {
    sgemm_body<NPTS, P1, CIN, false>(g_featT, g_W1aT, g_ZT, nullptr, nullptr);
}
__global__ void __launch_bounds__(256) gemmB_kernel() {
    sgemm_body<MPTS, P1, CORIG, false>(g_origT, g_W1bT, g_y1, nullptr, nullptr);
}
__global__ void __launch_bounds__(256) gemm2_kernel() {
    sgemm_body<MPTS, P2, P1, true>(g_y1, g_W2T, g_y2, g_a1, g_b1);
}

// ---------------- combine: y1 += sum_k w_k * ZT[i_k][:], fused BN1 stats ----------------
__global__ void combine_stats_kernel() {
    int f = blockIdx.y, t = f & 3;
    int m0 = blockIdx.x * 32;
    int o = threadIdx.x;
    const float* Z = g_ZT + (size_t)f * NPTS * P1;
    float s = 0.f, q = 0.f;
    #pragma unroll 4
    for (int mm = 0; mm < 32; mm++) {
        int m = m0 + mm;
        size_t ib = ((size_t)f * MPTS + m) * 3;
        int   i0 = g_idx[ib], i1 = g_idx[ib + 1], i2 = g_idx[ib + 2];
        float w0 = g_w[ib],   w1 = g_w[ib + 1],   w2 = g_w[ib + 2];
        size_t yi = ((size_t)f * MPTS + m) * P1 + o;
        float v = g_y1[yi];
        v = fmaf(w0, Z[(size_t)i0 * P1 + o], v);
        v = fmaf(w1, Z[(size_t)i1 * P1 + o], v);
        v = fmaf(w2, Z[(size_t)i2 * P1 + o], v);
        g_y1[yi] = v;
        s += v; q = fmaf(v, v, q);
    }
    atomicAdd(&g_sum1[t * P1 + o], s);
    atomicAdd(&g_sq1 [t * P1 + o], q);
}

// ---------------- BN2 stats over raw y2 ----------------
__global__ void stats2_kernel() {
    int f = blockIdx.y, t = f & 3, o = threadIdx.x, m0 = blockIdx.x * 32;
    const float* y = g_y2 + ((size_t)f * MPTS + m0) * P2 + o;
    float s = 0.f, q = 0.f;
    #pragma unroll 4
    for (int mm = 0; mm < 32; mm++) {
        float v = y[(size_t)mm * P2];
        s += v; q = fmaf(v, v, q);
    }
    atomicAdd(&g_sum2[t * P2 + o], s);
    atomicAdd(&g_sq2 [t * P2 + o], q);
}

// ---------------- finalize BN coefficients: a = gamma*rsqrt(var+eps), b = beta - mean*a ----
__global__ void finalize_kernel(int which, const float* __restrict__ gamma,
                                const float* __restrict__ beta) {
    int i = blockIdx.x * 256 + threadIdx.x;   // 0..1023
    if (i >= TT * P1) return;
    const float rcnt = 1.0f / (float)(BB * MPTS);
    float sum = (which == 1) ? g_sum1[i] : g_sum2[i];
    float sq  = (which == 1) ? g_sq1[i]  : g_sq2[i];
    float mean = sum * rcnt;
    float var  = fmaf(-mean, mean, sq * rcnt);
    int o = i & 255;
    float a = gamma[o] * rsqrtf(var + EPS_BN);
    float b = fmaf(-mean, a, beta[o]);
    if (which == 1) { g_a1[i] = a; g_b1[i] = b; }
    else            { g_a2[i] = a; g_b2[i] = b; }
}

// ---------------- output: BN2+ReLU + transpose [f][m][o] -> [f][o][m] ----------------
__global__ void output_kernel(float* __restrict__ out) {
    __shared__ float tile[32][33];
    int f = blockIdx.z, t = f & 3;
    int m0 = blockIdx.x * 32, o0 = blockIdx.y * 32;
    int tx = threadIdx.x, ty = threadIdx.y;            // 32 x 8
    #pragma unroll
    for (int i = ty; i < 32; i += 8) {
        int o = o0 + tx;
        float v = g_y2[((size_t)f * MPTS + m0 + i) * P2 + o];
        tile[i][tx] = fmaxf(0.f, fmaf(g_a2[t * P2 + o], v, g_b2[t * P2 + o]));
    }
    __syncthreads();
    #pragma unroll
    for (int i = ty; i < 32; i += 8)
        out[((size_t)f * P2 + o0 + i) * MPTS + m0 + tx] = tile[tx][i];
}

// ---------------- launch ----------------
extern "C" void kernel_launch(void* const* d_in, const int* in_sizes, int n_in,
                              void* d_out, int out_size) {
    const float* xyzs   = (const float*)d_in[0];
    const float* oxyzs  = (const float*)d_in[1];
    const float* feats  = (const float*)d_in[2];
    const float* ofeat  = (const float*)d_in[3];
    const float* W1     = (const float*)d_in[4];
    const float* gamma1 = (const float*)d_in[5];
    const float* beta1  = (const float*)d_in[6];
    const float* W2     = (const float*)d_in[7];
    const float* gamma2 = (const float*)d_in[8];
    const float* beta2  = (const float*)d_in[9];
    float* out = (float*)d_out;

    const int xyz_elems = FRAMES * MPTS * 3;       // 393216
    const int x_elems   = FRAMES * P2 * MPTS;      // 33554432
    float* out_x = out;
    if (out_size >= xyz_elems + x_elems) {
        // tuple output: original_xyzs passthrough first, then x
        cudaMemcpyAsync(out, oxyzs, (size_t)xyz_elems * sizeof(float),
                        cudaMemcpyDeviceToDevice, 0);
        out_x = out + xyz_elems;
    }

    prep_kernel<<<384, 256>>>(W1, W2);
    knn_kernel<<<dim3(MPTS / 256, FRAMES), 256>>>(xyzs, oxyzs);
    transpose_kernel<<<dim3(NPTS / 32, CIN / 32, FRAMES),  dim3(32, 8)>>>(feats, CIN,   NPTS, 0);
    transpose_kernel<<<dim3(MPTS / 32, CORIG / 32, FRAMES), dim3(32, 8)>>>(ofeat, CORIG, MPTS, 1);

    gemmZ_kernel<<<dim3(P1 / 128, NPTS / 128, FRAMES), 256>>>();   // Z = featT @ W1a^T
    gemmB_kernel<<<dim3(P1 / 128, MPTS / 128, FRAMES), 256>>>();   // y1 = origT @ W1b^T
    combine_stats_kernel<<<dim3(MPTS / 32, FRAMES), 256>>>();      // y1 += gather(Z); stats1
    finalize_kernel<<<4, 256>>>(1, gamma1, beta1);

    gemm2_kernel<<<dim3(P2 / 128, MPTS / 128, FRAMES), 256>>>();   // y2 = relu(bn1(y1)) @ W2^T
    stats2_kernel<<<dim3(MPTS / 32, FRAMES), 256>>>();
    finalize_kernel<<<4, 256>>>(2, gamma2, beta2);

    output_kernel<<<dim3(MPTS / 32, P2 / 32, FRAMES), dim3(32, 8)>>>(out_x);
}

// round 3
// speedup vs baseline: 1.6135x; 1.6135x over previous
#include <cuda_runtime.h>
#include <cuda_bf16.h>
#include <stdint.h>
#include <math.h>

// ---------------- problem constants ----------------
#define BB      8
#define TT      4
#define NPTS    1024
#define MPTS    4096
#define CIN     256
#define CORIG   128
#define CCAT    384
#define P1      256
#define P2      256
#define FRAMES  32          // B*T
#define EPS_D   1e-8f
#define EPS_BN  1e-5f

// ---------------- scratch (device globals, no runtime alloc) ----------------
__device__ __align__(16) int   g_idx[FRAMES * MPTS * 3];
__device__ __align__(16) float g_w  [FRAMES * MPTS * 3];
__device__ __align__(16) float g_featT[(size_t)FRAMES * NPTS * CIN];    // [f][n][c]
__device__ __align__(16) float g_origT[(size_t)FRAMES * MPTS * CORIG];  // [f][m][c]
__device__ __align__(16) float g_ZT   [(size_t)FRAMES * NPTS * P1];     // [f][n][o]
__device__ __align__(16) float g_y1   [(size_t)FRAMES * MPTS * P1];     // [f][m][o]
__device__ __align__(16) float g_y2   [(size_t)FRAMES * MPTS * P2];     // [f][m][o]
// bf16 split weights, [k][n] layout (n contiguous) for ldmatrix.trans B feed
__device__ __align__(16) __nv_bfloat16 g_W1a_h[CIN * P1],   g_W1a_l[CIN * P1];
__device__ __align__(16) __nv_bfloat16 g_W1b_h[CORIG * P1], g_W1b_l[CORIG * P1];
__device__ __align__(16) __nv_bfloat16 g_W2_h [P1 * P2],    g_W2_l [P1 * P2];
__device__ float g_sum1[TT * P1], g_sq1[TT * P1], g_a1[TT * P1], g_b1[TT * P1];
__device__ float g_sum2[TT * P2], g_sq2[TT * P2], g_a2[TT * P2], g_b2[TT * P2];

// ---------------- helpers ----------------
__device__ __forceinline__ uint32_t smem_u32(const void* p) {
    uint32_t a;
    asm("{ .reg .u64 t; cvta.to.shared.u64 t, %1; cvt.u32.u64 %0, t; }" : "=r"(a) : "l"(p));
    return a;
}

#define LDMX4(r, addr) \
    asm volatile("ldmatrix.sync.aligned.m8n8.x4.shared.b16 {%0,%1,%2,%3}, [%4];" \
        : "=r"((r)[0]), "=r"((r)[1]), "=r"((r)[2]), "=r"((r)[3]) : "r"(addr))

#define LDMX4T(r, addr) \
    asm volatile("ldmatrix.sync.aligned.m8n8.x4.trans.shared.b16 {%0,%1,%2,%3}, [%4];" \
        : "=r"((r)[0]), "=r"((r)[1]), "=r"((r)[2]), "=r"((r)[3]) : "r"(addr))

#define MMA_BF16(d, a, b0, b1) \
    asm volatile("mma.sync.aligned.m16n8k16.row.col.f32.bf16.bf16.f32 " \
        "{%0,%1,%2,%3},{%4,%5,%6,%7},{%8,%9},{%0,%1,%2,%3};" \
        : "+f"((d)[0]), "+f"((d)[1]), "+f"((d)[2]), "+f"((d)[3]) \
        : "r"((a)[0]), "r"((a)[1]), "r"((a)[2]), "r"((a)[3]), "r"(b0), "r"(b1))

__device__ __forceinline__ void split2(float a, float b, uint32_t& h, uint32_t& l) {
    __nv_bfloat162 hb = __floats2bfloat162_rn(a, b);
    float2 hf = __bfloat1622float2(hb);
    __nv_bfloat162 lb = __floats2bfloat162_rn(a - hf.x, b - hf.y);
    h = *reinterpret_cast<uint32_t*>(&hb);
    l = *reinterpret_cast<uint32_t*>(&lb);
}

// ---------------- prep: zero stats, split weights to bf16 hi/lo, [k][n] ----------------
__global__ void prep_kernel(const float* __restrict__ W1, const float* __restrict__ W2) {
    int i = blockIdx.x * 256 + threadIdx.x;
    if (i < TT * P1) { g_sum1[i] = 0.f; g_sq1[i] = 0.f; g_sum2[i] = 0.f; g_sq2[i] = 0.f; }
    if (i < P1 * CCAT) {
        int o = i / CCAT, c = i % CCAT;
        float v = W1[i];
        __nv_bfloat16 h = __float2bfloat16_rn(v);
        __nv_bfloat16 l = __float2bfloat16_rn(v - __bfloat162float(h));
        if (c < CIN) { g_W1a_h[c * P1 + o] = h; g_W1a_l[c * P1 + o] = l; }
        else { g_W1b_h[(c - CIN) * P1 + o] = h; g_W1b_l[(c - CIN) * P1 + o] = l; }
    }
    if (i < P2 * P1) {
        int o = i / P1, c = i % P1;
        float v = W2[i];
        __nv_bfloat16 h = __float2bfloat16_rn(v);
        g_W2_h[c * P2 + o] = h;
        g_W2_l[c * P2 + o] = __float2bfloat16_rn(v - __bfloat162float(h));
    }
}

// ---------------- three_nn ----------------
__global__ void knn_kernel(const float* __restrict__ xyzs, const float* __restrict__ oxyzs) {
    __shared__ float sx[NPTS], sy[NPTS], sz[NPTS];
    int f = blockIdx.y;
    const float* p = xyzs + (size_t)f * NPTS * 3;
    for (int i = threadIdx.x; i < NPTS; i += 256) {
        sx[i] = p[3 * i]; sy[i] = p[3 * i + 1]; sz[i] = p[3 * i + 2];
    }
    __syncthreads();
    int m = blockIdx.x * 256 + threadIdx.x;
    const float* q = oxyzs + ((size_t)f * MPTS + m) * 3;
    float qx = q[0], qy = q[1], qz = q[2];
    float b0 = 1e30f, b1 = 1e30f, b2 = 1e30f;
    int   i0 = 0,     i1 = 0,     i2 = 0;
    #pragma unroll 4
    for (int n = 0; n < NPTS; n++) {
        float dx = qx - sx[n], dy = qy - sy[n], dz = qz - sz[n];
        float d = fmaf(dx, dx, fmaf(dy, dy, dz * dz));
        if (d < b2) {
            if (d < b1) {
                b2 = b1; i2 = i1;
                if (d < b0) { b1 = b0; i1 = i0; b0 = d; i0 = n; }
                else        { b1 = d;  i1 = n; }
            } else { b2 = d; i2 = n; }
        }
    }
    float w0 = 1.f / (b0 + EPS_D), w1 = 1.f / (b1 + EPS_D), w2 = 1.f / (b2 + EPS_D);
    float inv = 1.f / (w0 + w1 + w2);
    size_t base = ((size_t)f * MPTS + m) * 3;
    g_idx[base] = i0; g_idx[base + 1] = i1; g_idx[base + 2] = i2;
    g_w[base] = w0 * inv; g_w[base + 1] = w1 * inv; g_w[base + 2] = w2 * inv;
}

// ---------------- tiled transpose  in[f][R][Cc] -> out[f][Cc][R] ----------------
__global__ void transpose_kernel(const float* __restrict__ in, int R, int Cc, int which) {
    __shared__ float tile[32][33];
    float* outg = which ? g_origT : g_featT;
    int f = blockIdx.z;
    const float* A = in   + (size_t)f * R * Cc;
    float*       O = outg + (size_t)f * R * Cc;
    int c0 = blockIdx.x * 32, r0 = blockIdx.y * 32;
    int tx = threadIdx.x, ty = threadIdx.y;            // 32 x 8
    #pragma unroll
    for (int i = ty; i < 32; i += 8)
        tile[i][tx] = A[(size_t)(r0 + i) * Cc + c0 + tx];
    __syncthreads();
    #pragma unroll
    for (int i = ty; i < 32; i += 8)
        O[(size_t)(c0 + i) * R + r0 + tx] = tile[tx][i];
}

// ---------------- HMMA GEMM: C[f][M][256] = A[f][M][K] @ W[K][256] ----------------
// bf16 hi/lo split (3 mma terms), fp32 accum. Optional fused BN+ReLU on A.
// CTA tile 64x128, 8 warps (2x4), warp tile 32x32, K chunk 32, double-buffered.
// SMEM layout (bytes): Ah[2][64][40]=10240 | Al=10240 | Bh[2][32][136]=17408 |
//                      Bl=17408 | s_sc 1024 | s_bi 1024   -> 57344 total
#define SM_AL 10240
#define SM_BH 20480
#define SM_BL 37888
#define SM_SC 55296
#define SM_BI 56320
#define SMEM_G 57344

template <int K, bool BN>
__device__ __forceinline__ void gemm_mma(const float* __restrict__ Aall,
                                         const __nv_bfloat16* __restrict__ Bh,
                                         const __nv_bfloat16* __restrict__ Bl,
                                         float* __restrict__ Call,
                                         const float* __restrict__ aa,
                                         const float* __restrict__ bb) {
    extern __shared__ char sm[];
    const uint32_t sbase = smem_u32(sm);
    constexpr int NC = K / 32;

    const int tid = threadIdx.x;
    const int l   = tid & 31;
    const int wid = tid >> 5;
    const int wm  = wid >> 2;       // 0..1
    const int wn  = wid & 3;        // 0..3
    const int f   = blockIdx.z, t = f & 3;
    const int bm  = blockIdx.y * 64;
    const int bn  = blockIdx.x * 128;
    const size_t Mtot = (size_t)gridDim.y * 64;
    const float* A = Aall + (size_t)f * Mtot * K;
    float*       C = Call + (size_t)f * Mtot * 256;

    float* s_sc = (float*)(sm + SM_SC);
    float* s_bi = (float*)(sm + SM_BI);
    if (BN) {
        s_sc[tid] = aa[t * 256 + tid];
        s_bi[tid] = bb[t * 256 + tid];
        __syncthreads();
    }

    // global-load assignments
    const int arow = tid >> 2, acg = (tid & 3) * 8;       // A: 64 rows x 32k, 8 floats/thr
    const int bk   = tid >> 3, bng = (tid & 7) * 16;      // B: 32k x 128n, 16 bf16/thr
    const float* Aptr = A + (size_t)(bm + arow) * K + acg;
    const __nv_bfloat16* Bhp = Bh + (size_t)bk * 256 + bn + bng;
    const __nv_bfloat16* Blp = Bl + (size_t)bk * 256 + bn + bng;

    // ldmatrix lane offsets
    const uint32_t aoff = (uint32_t)(((l & 15) * 40 + (l >> 4) * 8) * 2) + (uint32_t)wm * 2560u;
    const uint32_t boff = (uint32_t)((((l & 7) + ((l >> 3) & 1) * 8) * 136 +
                                      ((l >> 4) * 8) + wn * 32) * 2);

    float acc[2][4][4];
    #pragma unroll
    for (int i = 0; i < 2; i++)
        #pragma unroll
        for (int j = 0; j < 4; j++)
            #pragma unroll
            for (int k = 0; k < 4; k++) acc[i][j][k] = 0.f;

    float4 ra0, ra1; uint4 rbh0, rbh1, rbl0, rbl1;

    auto loadregs = [&](int kc) {
        const float* ap = Aptr + kc * 32;
        ra0 = *(const float4*)ap;
        ra1 = *(const float4*)(ap + 4);
        const __nv_bfloat16* bhp = Bhp + (size_t)kc * 32 * 256;
        const __nv_bfloat16* blp = Blp + (size_t)kc * 32 * 256;
        rbh0 = *(const uint4*)bhp;  rbh1 = *(const uint4*)(bhp + 8);
        rbl0 = *(const uint4*)blp;  rbl1 = *(const uint4*)(blp + 8);
    };
    auto storestage = [&](int buf, int kc) {
        float4 v0 = ra0, v1 = ra1;
        if (BN) {
            int cc = kc * 32 + acg;
            v0.x = fmaxf(0.f, fmaf(s_sc[cc + 0], v0.x, s_bi[cc + 0]));
            v0.y = fmaxf(0.f, fmaf(s_sc[cc + 1], v0.y, s_bi[cc + 1]));
            v0.z = fmaxf(0.f, fmaf(s_sc[cc + 2], v0.z, s_bi[cc + 2]));
            v0.w = fmaxf(0.f, fmaf(s_sc[cc + 3], v0.w, s_bi[cc + 3]));
            v1.x = fmaxf(0.f, fmaf(s_sc[cc + 4], v1.x, s_bi[cc + 4]));
            v1.y = fmaxf(0.f, fmaf(s_sc[cc + 5], v1.y, s_bi[cc + 5]));
            v1.z = fmaxf(0.f, fmaf(s_sc[cc + 6], v1.z, s_bi[cc + 6]));
            v1.w = fmaxf(0.f, fmaf(s_sc[cc + 7], v1.w, s_bi[cc + 7]));
        }
        uint32_t h0, l0, h1, l1, h2, l2, h3, l3;
        split2(v0.x, v0.y, h0, l0); split2(v0.z, v0.w, h1, l1);
        split2(v1.x, v1.y, h2, l2); split2(v1.z, v1.w, h3, l3);
        uint32_t ao = (uint32_t)(buf * 5120 + arow * 80 + acg * 2);
        *(uint4*)(sm + ao)         = make_uint4(h0, h1, h2, h3);
        *(uint4*)(sm + SM_AL + ao) = make_uint4(l0, l1, l2, l3);
        uint32_t bo = (uint32_t)(buf * 8704 + bk * 272 + bng * 2);
        *(uint4*)(sm + SM_BH + bo)      = rbh0;
        *(uint4*)(sm + SM_BH + bo + 16) = rbh1;
        *(uint4*)(sm + SM_BL + bo)      = rbl0;
        *(uint4*)(sm + SM_BL + bo + 16) = rbl1;
    };
    auto compute = [&](int buf) {
        const uint32_t sa_h = sbase + buf * 5120 + aoff;
        const uint32_t sa_l = sbase + SM_AL + buf * 5120 + aoff;
        const uint32_t sb_h = sbase + SM_BH + buf * 8704 + boff;
        const uint32_t sb_l = sbase + SM_BL + buf * 8704 + boff;
        #pragma unroll
        for (int ks = 0; ks < 2; ks++) {
            uint32_t ah0[4], ah1[4], al0[4], al1[4];
            LDMX4(ah0, sa_h + ks * 32);
            LDMX4(ah1, sa_h + 1280 + ks * 32);
            LDMX4(al0, sa_l + ks * 32);
            LDMX4(al1, sa_l + 1280 + ks * 32);
            #pragma unroll
            for (int nf = 0; nf < 2; nf++) {
                uint32_t bh[4], bl[4];
                LDMX4T(bh, sb_h + nf * 32 + ks * 4352);
                LDMX4T(bl, sb_l + nf * 32 + ks * 4352);
                const int n0 = nf * 2, n1 = nf * 2 + 1;
                MMA_BF16(acc[0][n0], ah0, bh[0], bh[1]);
                MMA_BF16(acc[0][n1], ah0, bh[2], bh[3]);
                MMA_BF16(acc[1][n0], ah1, bh[0], bh[1]);
                MMA_BF16(acc[1][n1], ah1, bh[2], bh[3]);
                MMA_BF16(acc[0][n0], ah0, bl[0], bl[1]);
                MMA_BF16(acc[0][n1], ah0, bl[2], bl[3]);
                MMA_BF16(acc[1][n0], ah1, bl[0], bl[1]);
                MMA_BF16(acc[1][n1], ah1, bl[2], bl[3]);
                MMA_BF16(acc[0][n0], al0, bh[0], bh[1]);
                MMA_BF16(acc[0][n1], al0, bh[2], bh[3]);
                MMA_BF16(acc[1][n0], al1, bh[0], bh[1]);
                MMA_BF16(acc[1][n1], al1, bh[2], bh[3]);
            }
        }
    };

    loadregs(0);
    storestage(0, 0);
    __syncthreads();
    for (int kc = 0; kc < NC; kc++) {
        if (kc + 1 < NC) loadregs(kc + 1);
        compute(kc & 1);
        if (kc + 1 < NC) {
            storestage((kc + 1) & 1, kc + 1);
            __syncthreads();
        }
    }

    // epilogue: direct fp32 stores
    #pragma unroll
    for (int mi = 0; mi < 2; mi++) {
        #pragma unroll
        for (int ni = 0; ni < 4; ni++) {
            int row = bm + wm * 32 + mi * 16 + (l >> 2);
            int col = bn + wn * 32 + ni * 8 + (l & 3) * 2;
            float* cp = C + (size_t)row * 256 + col;
            *(float2*)cp = make_float2(acc[mi][ni][0], acc[mi][ni][1]);
            *(float2*)(cp + 8 * 256) = make_float2(acc[mi][ni][2], acc[mi][ni][3]);
        }
    }
}

__global__ void __launch_bounds__(256, 2) gemmZ_mma() {
    gemm_mma<CIN, false>(g_featT, g_W1a_h, g_W1a_l, g_ZT, nullptr, nullptr);
}
__global__ void __launch_bounds__(256, 2) gemmB_mma() {
    gemm_mma<CORIG, false>(g_origT, g_W1b_h, g_W1b_l, g_y1, nullptr, nullptr);
}
__global__ void __launch_bounds__(256, 2) gemm2_mma() {
    gemm_mma<P1, true>(g_y1, g_W2_h, g_W2_l, g_y2, g_a1, g_b1);
}

// ---------------- combine: y1 += sum_k w_k * ZT[i_k][:], fused BN1 stats ----------------
__global__ void combine_stats_kernel() {
    int f = blockIdx.y, t = f & 3;
    int m0 = blockIdx.x * 32;
    int o = threadIdx.x;
    const float* Z = g_ZT + (size_t)f * NPTS * P1;
    float s = 0.f, q = 0.f;
    #pragma unroll 4
    for (int mm = 0; mm < 32; mm++) {
        int m = m0 + mm;
        size_t ib = ((size_t)f * MPTS + m) * 3;
        int   i0 = g_idx[ib], i1 = g_idx[ib + 1], i2 = g_idx[ib + 2];
        float w0 = g_w[ib],   w1 = g_w[ib + 1],   w2 = g_w[ib + 2];
        size_t yi = ((size_t)f * MPTS + m) * P1 + o;
        float v = g_y1[yi];
        v = fmaf(w0, Z[(size_t)i0 * P1 + o], v);
        v = fmaf(w1, Z[(size_t)i1 * P1 + o], v);
        v = fmaf(w2, Z[(size_t)i2 * P1 + o], v);
        g_y1[yi] = v;
        s += v; q = fmaf(v, v, q);
    }
    atomicAdd(&g_sum1[t * P1 + o], s);
    atomicAdd(&g_sq1 [t * P1 + o], q);
}

// ---------------- BN2 stats over raw y2 ----------------
__global__ void stats2_kernel() {
    int f = blockIdx.y, t = f & 3, o = threadIdx.x, m0 = blockIdx.x * 32;
    const float* y = g_y2 + ((size_t)f * MPTS + m0) * P2 + o;
    float s = 0.f, q = 0.f;
    #pragma unroll 4
    for (int mm = 0; mm < 32; mm++) {
        float v = y[(size_t)mm * P2];
        s += v; q = fmaf(v, v, q);
    }
    atomicAdd(&g_sum2[t * P2 + o], s);
    atomicAdd(&g_sq2 [t * P2 + o], q);
}

// ---------------- finalize BN coefficients ----------------
__global__ void finalize_kernel(int which, const float* __restrict__ gamma,
                                const float* __restrict__ beta) {
    int i = blockIdx.x * 256 + threadIdx.x;
    if (i >= TT * P1) return;
    const float rcnt = 1.0f / (float)(BB * MPTS);
    float sum = (which == 1) ? g_sum1[i] : g_sum2[i];
    float sq  = (which == 1) ? g_sq1[i]  : g_sq2[i];
    float mean = sum * rcnt;
    float var  = fmaf(-mean, mean, sq * rcnt);
    int o = i & 255;
    float a = gamma[o] * rsqrtf(var + EPS_BN);
    float b = fmaf(-mean, a, beta[o]);
    if (which == 1) { g_a1[i] = a; g_b1[i] = b; }
    else            { g_a2[i] = a; g_b2[i] = b; }
}

// ---------------- output: BN2+ReLU + transpose [f][m][o] -> [f][o][m] ----------------
__global__ void output_kernel(float* __restrict__ out) {
    __shared__ float tile[32][33];
    int f = blockIdx.z, t = f & 3;
    int m0 = blockIdx.x * 32, o0 = blockIdx.y * 32;
    int tx = threadIdx.x, ty = threadIdx.y;
    #pragma unroll
    for (int i = ty; i < 32; i += 8) {
        int o = o0 + tx;
        float v = g_y2[((size_t)f * MPTS + m0 + i) * P2 + o];
        tile[i][tx] = fmaxf(0.f, fmaf(g_a2[t * P2 + o], v, g_b2[t * P2 + o]));
    }
    __syncthreads();
    #pragma unroll
    for (int i = ty; i < 32; i += 8)
        out[((size_t)f * P2 + o0 + i) * MPTS + m0 + tx] = tile[tx][i];
}

// ---------------- launch ----------------
extern "C" void kernel_launch(void* const* d_in, const int* in_sizes, int n_in,
                              void* d_out, int out_size) {
    const float* xyzs   = (const float*)d_in[0];
    const float* oxyzs  = (const float*)d_in[1];
    const float* feats  = (const float*)d_in[2];
    const float* ofeat  = (const float*)d_in[3];
    const float* W1     = (const float*)d_in[4];
    const float* gamma1 = (const float*)d_in[5];
    const float* beta1  = (const float*)d_in[6];
    const float* W2     = (const float*)d_in[7];
    const float* gamma2 = (const float*)d_in[8];
    const float* beta2  = (const float*)d_in[9];
    float* out = (float*)d_out;

    (void)cudaFuncSetAttribute(gemmZ_mma, cudaFuncAttributeMaxDynamicSharedMemorySize, SMEM_G);
    (void)cudaFuncSetAttribute(gemmB_mma, cudaFuncAttributeMaxDynamicSharedMemorySize, SMEM_G);
    (void)cudaFuncSetAttribute(gemm2_mma, cudaFuncAttributeMaxDynamicSharedMemorySize, SMEM_G);

    const int xyz_elems = FRAMES * MPTS * 3;
    const int x_elems   = FRAMES * P2 * MPTS;
    float* out_x = out;
    if (out_size >= xyz_elems + x_elems) {
        cudaMemcpyAsync(out, oxyzs, (size_t)xyz_elems * sizeof(float),
                        cudaMemcpyDeviceToDevice, 0);
        out_x = out + xyz_elems;
    }

    prep_kernel<<<384, 256>>>(W1, W2);
    knn_kernel<<<dim3(MPTS / 256, FRAMES), 256>>>(xyzs, oxyzs);
    transpose_kernel<<<dim3(NPTS / 32, CIN / 32, FRAMES),   dim3(32, 8)>>>(feats, CIN,   NPTS, 0);
    transpose_kernel<<<dim3(MPTS / 32, CORIG / 32, FRAMES), dim3(32, 8)>>>(ofeat, CORIG, MPTS, 1);

    gemmZ_mma<<<dim3(2, NPTS / 64, FRAMES), 256, SMEM_G>>>();   // Z = featT @ W1a
    gemmB_mma<<<dim3(2, MPTS / 64, FRAMES), 256, SMEM_G>>>();   // y1 = origT @ W1b
    combine_stats_kernel<<<dim3(MPTS / 32, FRAMES), 256>>>();   // y1 += gather(Z); stats1
    finalize_kernel<<<4, 256>>>(1, gamma1, beta1);

    gemm2_mma<<<dim3(2, MPTS / 64, FRAMES), 256, SMEM_G>>>();   // y2 = relu(bn1(y1)) @ W2
    stats2_kernel<<<dim3(MPTS / 32, FRAMES), 256>>>();
    finalize_kernel<<<4, 256>>>(2, gamma2, beta2);

    output_kernel<<<dim3(MPTS / 32, P2 / 32, FRAMES), dim3(32, 8)>>>(out_x);
}

// round 5
// speedup vs baseline: 1.6179x; 1.0027x over previous
#include <cuda_runtime.h>
#include <cuda_bf16.h>
#include <stdint.h>
#include <math.h>

// ---------------- problem constants ----------------
#define BB      8
#define TT      4
#define NPTS    1024
#define MPTS    4096
#define CIN     256
#define CORIG   128
#define CCAT    384
#define P1      256
#define P2      256
#define FRAMES  32          // B*T
#define EPS_D   1e-8f
#define EPS_BN  1e-5f

// ---------------- scratch (device globals, no runtime alloc) ----------------
__device__ __align__(16) int   g_idx[FRAMES * MPTS * 3];
__device__ __align__(16) float g_w  [FRAMES * MPTS * 3];
__device__ __align__(16) float g_ZT [(size_t)FRAMES * NPTS * P1];     // [f][n][o]
__device__ __align__(16) float g_y1 [(size_t)FRAMES * MPTS * P1];     // [f][m][o]
__device__ __align__(16) float g_y2 [(size_t)FRAMES * MPTS * P2];     // [f][m][o]
// bf16 split weights, [k][n] layout (n contiguous) for ldmatrix.trans B feed
__device__ __align__(16) __nv_bfloat16 g_W1a_h[CIN * P1],   g_W1a_l[CIN * P1];
__device__ __align__(16) __nv_bfloat16 g_W1b_h[CORIG * P1], g_W1b_l[CORIG * P1];
__device__ __align__(16) __nv_bfloat16 g_W2_h [P1 * P2],    g_W2_l [P1 * P2];
__device__ float g_sum1[TT * P1], g_sq1[TT * P1], g_a1[TT * P1], g_b1[TT * P1];
__device__ float g_sum2[TT * P2], g_sq2[TT * P2], g_a2[TT * P2], g_b2[TT * P2];

// ---------------- helpers ----------------
__device__ __forceinline__ uint32_t smem_u32(const void* p) {
    uint32_t a;
    asm("{ .reg .u64 t; cvta.to.shared.u64 t, %1; cvt.u32.u64 %0, t; }" : "=r"(a) : "l"(p));
    return a;
}

#define LDMX4(r, addr) \
    asm volatile("ldmatrix.sync.aligned.m8n8.x4.shared.b16 {%0,%1,%2,%3}, [%4];" \
        : "=r"((r)[0]), "=r"((r)[1]), "=r"((r)[2]), "=r"((r)[3]) : "r"(addr))

#define LDMX4T(r, addr) \
    asm volatile("ldmatrix.sync.aligned.m8n8.x4.trans.shared.b16 {%0,%1,%2,%3}, [%4];" \
        : "=r"((r)[0]), "=r"((r)[1]), "=r"((r)[2]), "=r"((r)[3]) : "r"(addr))

#define MMA_BF16(d, a, b0, b1) \
    asm volatile("mma.sync.aligned.m16n8k16.row.col.f32.bf16.bf16.f32 " \
        "{%0,%1,%2,%3},{%4,%5,%6,%7},{%8,%9},{%0,%1,%2,%3};" \
        : "+f"((d)[0]), "+f"((d)[1]), "+f"((d)[2]), "+f"((d)[3]) \
        : "r"((a)[0]), "r"((a)[1]), "r"((a)[2]), "r"((a)[3]), "r"(b0), "r"(b1))

#define CP_ASYNC16(dst, src) \
    asm volatile("cp.async.cg.shared.global [%0], [%1], 16;" :: "r"(dst), "l"(src))
#define CP_COMMIT()  asm volatile("cp.async.commit_group;" ::: "memory")
#define CP_WAIT0()   asm volatile("cp.async.wait_group 0;" ::: "memory")

__device__ __forceinline__ void split2(float a, float b, uint32_t& h, uint32_t& l) {
    __nv_bfloat162 hb = __floats2bfloat162_rn(a, b);
    float2 hf = __bfloat1622float2(hb);
    __nv_bfloat162 lb = __floats2bfloat162_rn(a - hf.x, b - hf.y);
    h = *reinterpret_cast<uint32_t*>(&hb);
    l = *reinterpret_cast<uint32_t*>(&lb);
}

// ---------------- prep: zero stats, split weights to bf16 hi/lo, [k][n] ----------------
__global__ void prep_kernel(const float* __restrict__ W1, const float* __restrict__ W2) {
    int i = blockIdx.x * 256 + threadIdx.x;
    if (i < TT * P1) { g_sum1[i] = 0.f; g_sq1[i] = 0.f; g_sum2[i] = 0.f; g_sq2[i] = 0.f; }
    if (i < P1 * CCAT) {
        int o = i / CCAT, c = i % CCAT;
        float v = W1[i];
        __nv_bfloat16 h = __float2bfloat16_rn(v);
        __nv_bfloat16 l = __float2bfloat16_rn(v - __bfloat162float(h));
        if (c < CIN) { g_W1a_h[c * P1 + o] = h; g_W1a_l[c * P1 + o] = l; }
        else { g_W1b_h[(c - CIN) * P1 + o] = h; g_W1b_l[(c - CIN) * P1 + o] = l; }
    }
    if (i < P2 * P1) {
        int o = i / P1, c = i % P1;
        float v = W2[i];
        __nv_bfloat16 h = __float2bfloat16_rn(v);
        g_W2_h[c * P2 + o] = h;
        g_W2_l[c * P2 + o] = __float2bfloat16_rn(v - __bfloat162float(h));
    }
}

// ---------------- three_nn ----------------
__global__ void knn_kernel(const float* __restrict__ xyzs, const float* __restrict__ oxyzs) {
    __shared__ float sx[NPTS], sy[NPTS], sz[NPTS];
    int f = blockIdx.y;
    const float* p = xyzs + (size_t)f * NPTS * 3;
    for (int i = threadIdx.x; i < NPTS; i += 256) {
        sx[i] = p[3 * i]; sy[i] = p[3 * i + 1]; sz[i] = p[3 * i + 2];
    }
    __syncthreads();
    int m = blockIdx.x * 256 + threadIdx.x;
    const float* q = oxyzs + ((size_t)f * MPTS + m) * 3;
    float qx = q[0], qy = q[1], qz = q[2];
    float b0 = 1e30f, b1 = 1e30f, b2 = 1e30f;
    int   i0 = 0,     i1 = 0,     i2 = 0;
    #pragma unroll 4
    for (int n = 0; n < NPTS; n++) {
        float dx = qx - sx[n], dy = qy - sy[n], dz = qz - sz[n];
        float d = fmaf(dx, dx, fmaf(dy, dy, dz * dz));
        if (d < b2) {
            if (d < b1) {
                b2 = b1; i2 = i1;
                if (d < b0) { b1 = b0; i1 = i0; b0 = d; i0 = n; }
                else        { b1 = d;  i1 = n; }
            } else { b2 = d; i2 = n; }
        }
    }
    float w0 = 1.f / (b0 + EPS_D), w1 = 1.f / (b1 + EPS_D), w2 = 1.f / (b2 + EPS_D);
    float inv = 1.f / (w0 + w1 + w2);
    size_t base = ((size_t)f * MPTS + m) * 3;
    g_idx[base] = i0; g_idx[base + 1] = i1; g_idx[base + 2] = i2;
    g_w[base] = w0 * inv; g_w[base + 1] = w1 * inv; g_w[base + 2] = w2 * inv;
}

// ---------------- HMMA GEMM: C[f][M][256] = A @ W[K][256] ----------------
// CTA 64(M) x 256(N) full-N, 8 warps 2x4, warp tile 32x64, K chunk 32, dbl-buffered.
// B staged via cp.async (pre-split bf16, no transform needed).
// AMODE 0: A native [k][m] (m contiguous)  -> ldmatrix.trans feed
// AMODE 1: A row-major [m][k], fused BN1+ReLU on load
// FUSE  1: epilogue = stage acc -> smem, combine gather(Z)+stats1, write y1
// FUSE  2: epilogue = store C + fused stats2 reduction
#define SM_AL_OFF 10240
#define SM_BH_OFF 20480
#define SM_BL_OFF 54272
#define SM_SC_OFF 88064
#define SM_BI_OFF 89088
#define SMEM_G    90112

template <int K, int AMODE, int FUSE, int MTOT>
__device__ __forceinline__ void gemm_mma(const float* __restrict__ Aall,
                                         const __nv_bfloat16* __restrict__ Bhall,
                                         const __nv_bfloat16* __restrict__ Blall,
                                         float* __restrict__ Call) {
    extern __shared__ char sm[];
    const uint32_t sbase = smem_u32(sm);
    constexpr int NC = K / 32;

    const int tid = threadIdx.x;
    const int l   = tid & 31;
    const int wid = tid >> 5;
    const int wm  = wid >> 2;       // 0..1
    const int wn  = wid & 3;        // 0..3
    const int f   = blockIdx.y, t = f & 3;
    const int bm  = blockIdx.x * 64;
    const float* A = Aall + (size_t)f * MTOT * K;
    float*       C = Call + (size_t)f * MTOT * 256;

    float* s_sc = (float*)(sm + SM_SC_OFF);
    float* s_bi = (float*)(sm + SM_BI_OFF);
    if (AMODE == 1) {
        s_sc[tid] = g_a1[t * 256 + tid];
        s_bi[tid] = g_b1[t * 256 + tid];
        __syncthreads();
    }

    // global-load assignments
    const int arow = (AMODE == 1) ? (tid >> 2) : (tid >> 3);
    const int acg  = (AMODE == 1) ? ((tid & 3) * 8) : ((tid & 7) * 8);
    const int bk   = tid >> 3, bng = (tid & 7) * 32;     // B: 32 bf16 = 64B/thread
    const float* Aptr = (AMODE == 1)
        ? A + (size_t)(bm + arow) * K + acg
        : A + (size_t)arow * MTOT + bm + acg;
    const __nv_bfloat16* Bhp = Bhall + (size_t)bk * 256 + bng;
    const __nv_bfloat16* Blp = Blall + (size_t)bk * 256 + bng;
    const uint32_t bsto = (uint32_t)((bk * 264 + bng) * 2);

    // ldmatrix lane byte-offsets
    const uint32_t aoff = (AMODE == 1)
        ? (uint32_t)(((l & 15) * 40 + (l >> 4) * 8 + wm * 1280) * 2)
        : (uint32_t)((((l & 7) + ((l >> 4) & 1) * 8) * 72 + ((l >> 3) & 1) * 8 + wm * 32) * 2);
    const uint32_t boff = (uint32_t)((((l & 7) + ((l >> 3) & 1) * 8) * 264 +
                                      (l >> 4) * 8 + wn * 64) * 2);

    float acc[2][8][4];
    #pragma unroll
    for (int i = 0; i < 2; i++)
        #pragma unroll
        for (int j = 0; j < 8; j++)
            #pragma unroll
            for (int k = 0; k < 4; k++) acc[i][j][k] = 0.f;

    float4 ra0, ra1;

    auto issueB = [&](int kc, int buf) {
        const char* bhp = (const char*)(Bhp + (size_t)kc * 32 * 256);
        const char* blp = (const char*)(Blp + (size_t)kc * 32 * 256);
        uint32_t dh = sbase + SM_BH_OFF + buf * 16896 + bsto;
        uint32_t dl = sbase + SM_BL_OFF + buf * 16896 + bsto;
        #pragma unroll
        for (int j = 0; j < 4; j++) {
            CP_ASYNC16(dh + j * 16, bhp + j * 16);
            CP_ASYNC16(dl + j * 16, blp + j * 16);
        }
    };
    auto loadA = [&](int kc) {
        const float* ap = (AMODE == 1) ? (Aptr + kc * 32)
                                       : (Aptr + (size_t)kc * 32 * MTOT);
        ra0 = *(const float4*)ap;
        ra1 = *(const float4*)(ap + 4);
    };
    auto storeA = [&](int buf, int kc) {
        float4 v0 = ra0, v1 = ra1;
        if (AMODE == 1) {
            int cc = kc * 32 + acg;
            v0.x = fmaxf(0.f, fmaf(s_sc[cc + 0], v0.x, s_bi[cc + 0]));
            v0.y = fmaxf(0.f, fmaf(s_sc[cc + 1], v0.y, s_bi[cc + 1]));
            v0.z = fmaxf(0.f, fmaf(s_sc[cc + 2], v0.z, s_bi[cc + 2]));
            v0.w = fmaxf(0.f, fmaf(s_sc[cc + 3], v0.w, s_bi[cc + 3]));
            v1.x = fmaxf(0.f, fmaf(s_sc[cc + 4], v1.x, s_bi[cc + 4]));
            v1.y = fmaxf(0.f, fmaf(s_sc[cc + 5], v1.y, s_bi[cc + 5]));
            v1.z = fmaxf(0.f, fmaf(s_sc[cc + 6], v1.z, s_bi[cc + 6]));
            v1.w = fmaxf(0.f, fmaf(s_sc[cc + 7], v1.w, s_bi[cc + 7]));
        }
        uint32_t h0, l0, h1, l1, h2, l2, h3, l3;
        split2(v0.x, v0.y, h0, l0); split2(v0.z, v0.w, h1, l1);
        split2(v1.x, v1.y, h2, l2); split2(v1.z, v1.w, h3, l3);
        uint32_t ao = (uint32_t)(buf * 5120 +
            ((AMODE == 1) ? (arow * 40 + acg) : (arow * 72 + acg)) * 2);
        *(uint4*)(sm + ao)             = make_uint4(h0, h1, h2, h3);
        *(uint4*)(sm + SM_AL_OFF + ao) = make_uint4(l0, l1, l2, l3);
    };
    auto compute = [&](int buf) {
        #pragma unroll
        for (int ks = 0; ks < 2; ks++) {
            uint32_t ah[2][4], al[2][4];
            #pragma unroll
            for (int mi = 0; mi < 2; mi++) {
                if (AMODE == 1) {
                    uint32_t ad = sbase + buf * 5120 + aoff + mi * 1280 + ks * 32;
                    LDMX4(ah[mi], ad);
                    LDMX4(al[mi], ad + SM_AL_OFF);
                } else {
                    uint32_t ad = sbase + buf * 5120 + aoff + mi * 32 + ks * 2304;
                    LDMX4T(ah[mi], ad);
                    LDMX4T(al[mi], ad + SM_AL_OFF);
                }
            }
            #pragma unroll
            for (int nf = 0; nf < 4; nf++) {
                uint32_t bh[4], bl[4];
                uint32_t bd = sbase + SM_BH_OFF + buf * 16896 + boff + nf * 32 + ks * 8448;
                LDMX4T(bh, bd);
                LDMX4T(bl, bd + 33792);
                const int n0 = nf * 2, n1 = nf * 2 + 1;
                #pragma unroll
                for (int mi = 0; mi < 2; mi++) {
                    MMA_BF16(acc[mi][n0], ah[mi], bh[0], bh[1]);
                    MMA_BF16(acc[mi][n1], ah[mi], bh[2], bh[3]);
                    MMA_BF16(acc[mi][n0], ah[mi], bl[0], bl[1]);
                    MMA_BF16(acc[mi][n1], ah[mi], bl[2], bl[3]);
                    MMA_BF16(acc[mi][n0], al[mi], bh[0], bh[1]);
                    MMA_BF16(acc[mi][n1], al[mi], bh[2], bh[3]);
                }
            }
        }
    };

    issueB(0, 0); CP_COMMIT();
    loadA(0); storeA(0, 0);
    CP_WAIT0();
    __syncthreads();
    for (int kc = 0; kc < NC; kc++) {
        if (kc + 1 < NC) {
            issueB(kc + 1, (kc + 1) & 1); CP_COMMIT();
            loadA(kc + 1);
        }
        compute(kc & 1);
        if (kc + 1 < NC) {
            storeA((kc + 1) & 1, kc + 1);
            CP_WAIT0();
            __syncthreads();
        }
    }

    if (FUSE == 1) {
        // stage acc tile to smem fp32 [64][264], then combine+stats1+write y1
        __syncthreads();
        float* smf = (float*)sm;
        #pragma unroll
        for (int ni = 0; ni < 8; ni++) {
            int c = wn * 64 + ni * 8 + (l & 3) * 2;
            #pragma unroll
            for (int mi = 0; mi < 2; mi++) {
                int r = wm * 32 + mi * 16 + (l >> 2);
                *(float2*)&smf[r * 264 + c]       = make_float2(acc[mi][ni][0], acc[mi][ni][1]);
                *(float2*)&smf[(r + 8) * 264 + c] = make_float2(acc[mi][ni][2], acc[mi][ni][3]);
            }
        }
        __syncthreads();
        const int o = tid;
        const float* Z = g_ZT + (size_t)f * NPTS * 256;
        float s = 0.f, q = 0.f;
        #pragma unroll 4
        for (int r = 0; r < 64; r++) {
            int m = bm + r;
            size_t ib = ((size_t)f * MPTS + m) * 3;
            int   i0 = g_idx[ib], i1 = g_idx[ib + 1], i2 = g_idx[ib + 2];
            float w0 = g_w[ib],   w1 = g_w[ib + 1],   w2 = g_w[ib + 2];
            float v = smf[r * 264 + o];
            v = fmaf(w0, Z[(size_t)i0 * 256 + o], v);
            v = fmaf(w1, Z[(size_t)i1 * 256 + o], v);
            v = fmaf(w2, Z[(size_t)i2 * 256 + o], v);
            g_y1[((size_t)f * MPTS + m) * 256 + o] = v;
            s += v; q = fmaf(v, v, q);
        }
        atomicAdd(&g_sum1[t * 256 + o], s);
        atomicAdd(&g_sq1 [t * 256 + o], q);
    } else {
        #pragma unroll
        for (int ni = 0; ni < 8; ni++) {
            int col = wn * 64 + ni * 8 + (l & 3) * 2;
            float s0 = 0.f, q0 = 0.f, s1 = 0.f, q1 = 0.f;
            #pragma unroll
            for (int mi = 0; mi < 2; mi++) {
                int row = bm + wm * 32 + mi * 16 + (l >> 2);
                float v0 = acc[mi][ni][0], v1 = acc[mi][ni][1];
                float v2 = acc[mi][ni][2], v3 = acc[mi][ni][3];
                float* cp = C + (size_t)row * 256 + col;
                *(float2*)cp           = make_float2(v0, v1);
                *(float2*)(cp + 2048)  = make_float2(v2, v3);   // +8 rows * 256
                if (FUSE == 2) {
                    s0 += v0 + v2; s1 += v1 + v3;
                    q0 += fmaf(v0, v0, v2 * v2);
                    q1 += fmaf(v1, v1, v3 * v3);
                }
            }
            if (FUSE == 2) {
                #pragma unroll
                for (int d = 4; d < 32; d <<= 1) {
                    s0 += __shfl_xor_sync(0xffffffffu, s0, d);
                    s1 += __shfl_xor_sync(0xffffffffu, s1, d);
                    q0 += __shfl_xor_sync(0xffffffffu, q0, d);
                    q1 += __shfl_xor_sync(0xffffffffu, q1, d);
                }
                if (l < 4) {
                    atomicAdd(&g_sum2[t * 256 + col],     s0);
                    atomicAdd(&g_sum2[t * 256 + col + 1], s1);
                    atomicAdd(&g_sq2 [t * 256 + col],     q0);
                    atomicAdd(&g_sq2 [t * 256 + col + 1], q1);
                }
            }
        }
    }
}

__global__ void __launch_bounds__(256, 2) gemmZ_mma(const float* __restrict__ feats) {
    gemm_mma<CIN, 0, 0, NPTS>(feats, g_W1a_h, g_W1a_l, g_ZT);
}
__global__ void __launch_bounds__(256, 2) gemmB_mma(const float* __restrict__ ofeat) {
    gemm_mma<CORIG, 0, 1, MPTS>(ofeat, g_W1b_h, g_W1b_l, g_y1);
}
__global__ void __launch_bounds__(256, 2) gemm2_mma() {
    gemm_mma<P1, 1, 2, MPTS>(g_y1, g_W2_h, g_W2_l, g_y2);
}

// ---------------- finalize BN coefficients ----------------
__global__ void finalize_kernel(int which, const float* __restrict__ gamma,
                                const float* __restrict__ beta) {
    int i = blockIdx.x * 256 + threadIdx.x;
    if (i >= TT * P1) return;
    const float rcnt = 1.0f / (float)(BB * MPTS);
    float sum = (which == 1) ? g_sum1[i] : g_sum2[i];
    float sq  = (which == 1) ? g_sq1[i]  : g_sq2[i];
    float mean = sum * rcnt;
    float var  = fmaf(-mean, mean, sq * rcnt);
    int o = i & 255;
    float a = gamma[o] * rsqrtf(var + EPS_BN);
    float b = fmaf(-mean, a, beta[o]);
    if (which == 1) { g_a1[i] = a; g_b1[i] = b; }
    else            { g_a2[i] = a; g_b2[i] = b; }
}

// ---------------- output: BN2+ReLU + transpose [f][m][o] -> [f][o][m] ----------------
__global__ void output_kernel(float* __restrict__ out) {
    __shared__ float tile[32][33];
    int f = blockIdx.z, t = f & 3;
    int m0 = blockIdx.x * 32, o0 = blockIdx.y * 32;
    int tx = threadIdx.x, ty = threadIdx.y;
    #pragma unroll
    for (int i = ty; i < 32; i += 8) {
        int o = o0 + tx;
        float v = g_y2[((size_t)f * MPTS + m0 + i) * P2 + o];
        tile[i][tx] = fmaxf(0.f, fmaf(g_a2[t * P2 + o], v, g_b2[t * P2 + o]));
    }
    __syncthreads();
    #pragma unroll
    for (int i = ty; i < 32; i += 8)
        out[((size_t)f * P2 + o0 + i) * MPTS + m0 + tx] = tile[tx][i];
}

// ---------------- launch ----------------
extern "C" void kernel_launch(void* const* d_in, const int* in_sizes, int n_in,
                              void* d_out, int out_size) {
    const float* xyzs   = (const float*)d_in[0];
    const float* oxyzs  = (const float*)d_in[1];
    const float* feats  = (const float*)d_in[2];
    const float* ofeat  = (const float*)d_in[3];
    const float* W1     = (const float*)d_in[4];
    const float* gamma1 = (const float*)d_in[5];
    const float* beta1  = (const float*)d_in[6];
    const float* W2     = (const float*)d_in[7];
    const float* gamma2 = (const float*)d_in[8];
    const float* beta2  = (const float*)d_in[9];
    float* out = (float*)d_out;

    (void)cudaFuncSetAttribute(gemmZ_mma, cudaFuncAttributeMaxDynamicSharedMemorySize, SMEM_G);
    (void)cudaFuncSetAttribute(gemmB_mma, cudaFuncAttributeMaxDynamicSharedMemorySize, SMEM_G);
    (void)cudaFuncSetAttribute(gemm2_mma, cudaFuncAttributeMaxDynamicSharedMemorySize, SMEM_G);

    const int xyz_elems = FRAMES * MPTS * 3;
    const int x_elems   = FRAMES * P2 * MPTS;
    float* out_x = out;
    if (out_size >= xyz_elems + x_elems) {
        cudaMemcpyAsync(out, oxyzs, (size_t)xyz_elems * sizeof(float),
                        cudaMemcpyDeviceToDevice, 0);
        out_x = out + xyz_elems;
    }

    prep_kernel<<<384, 256>>>(W1, W2);
    knn_kernel<<<dim3(MPTS / 256, FRAMES), 256>>>(xyzs, oxyzs);

    gemmZ_mma<<<dim3(NPTS / 64, FRAMES), 256, SMEM_G>>>(feats);   // Z = feats^T @ W1a
    gemmB_mma<<<dim3(MPTS / 64, FRAMES), 256, SMEM_G>>>(ofeat);   // y1 = ofeat^T@W1b + gather(Z); stats1
    finalize_kernel<<<4, 256>>>(1, gamma1, beta1);

    gemm2_mma<<<dim3(MPTS / 64, FRAMES), 256, SMEM_G>>>();        // y2 = relu(bn1(y1)) @ W2; stats2
    finalize_kernel<<<4, 256>>>(2, gamma2, beta2);

    output_kernel<<<dim3(MPTS / 32, P2 / 32, FRAMES), dim3(32, 8)>>>(out_x);
}

// round 6
// speedup vs baseline: 1.9336x; 1.1952x over previous
#include <cuda_runtime.h>
#include <cuda_bf16.h>
#include <stdint.h>
#include <math.h>

// ---------------- problem constants ----------------
#define BB      8
#define TT      4
#define NPTS    1024
#define MPTS    4096
#define CIN     256
#define CORIG   128
#define CCAT    384
#define P1      256
#define P2      256
#define FRAMES  32          // B*T
#define EPS_D   1e-8f
#define EPS_BN  1e-5f

// ---------------- scratch (device globals, no runtime alloc) ----------------
__device__ __align__(16) int   g_idx[FRAMES * MPTS * 3];
__device__ __align__(16) float g_w  [FRAMES * MPTS * 3];
__device__ __align__(16) float g_ZT [(size_t)FRAMES * NPTS * P1];     // [f][n][o]
__device__ __align__(16) float g_y1 [(size_t)FRAMES * MPTS * P1];     // [f][m][o]
__device__ __align__(16) float g_y2 [(size_t)FRAMES * MPTS * P2];     // [f][m][o]
// bf16 split weights, [k][n] layout (n contiguous)
__device__ __align__(16) __nv_bfloat16 g_W1a_h[CIN * P1],   g_W1a_l[CIN * P1];
__device__ __align__(16) __nv_bfloat16 g_W1b_h[CORIG * P1], g_W1b_l[CORIG * P1];
__device__ __align__(16) __nv_bfloat16 g_W2_h [P1 * P2],    g_W2_l [P1 * P2];
__device__ float g_sum1[TT * P1], g_sq1[TT * P1], g_a1[TT * P1], g_b1[TT * P1];
__device__ float g_sum2[TT * P2], g_sq2[TT * P2], g_a2[TT * P2], g_b2[TT * P2];

// ---------------- helpers ----------------
__device__ __forceinline__ uint32_t smem_u32(const void* p) {
    uint32_t a;
    asm("{ .reg .u64 t; cvta.to.shared.u64 t, %1; cvt.u32.u64 %0, t; }" : "=r"(a) : "l"(p));
    return a;
}

#define LDMX4(r, addr) \
    asm volatile("ldmatrix.sync.aligned.m8n8.x4.shared.b16 {%0,%1,%2,%3}, [%4];" \
        : "=r"((r)[0]), "=r"((r)[1]), "=r"((r)[2]), "=r"((r)[3]) : "r"(addr))

#define LDMX4T(r, addr) \
    asm volatile("ldmatrix.sync.aligned.m8n8.x4.trans.shared.b16 {%0,%1,%2,%3}, [%4];" \
        : "=r"((r)[0]), "=r"((r)[1]), "=r"((r)[2]), "=r"((r)[3]) : "r"(addr))

#define MMA_BF16(d, a, b0, b1) \
    asm volatile("mma.sync.aligned.m16n8k16.row.col.f32.bf16.bf16.f32 " \
        "{%0,%1,%2,%3},{%4,%5,%6,%7},{%8,%9},{%0,%1,%2,%3};" \
        : "+f"((d)[0]), "+f"((d)[1]), "+f"((d)[2]), "+f"((d)[3]) \
        : "r"((a)[0]), "r"((a)[1]), "r"((a)[2]), "r"((a)[3]), "r"(b0), "r"(b1))

#define CP_ASYNC16(dst, src) \
    asm volatile("cp.async.cg.shared.global [%0], [%1], 16;" :: "r"(dst), "l"(src))
#define CP_COMMIT()  asm volatile("cp.async.commit_group;" ::: "memory")
#define CP_WAIT0()   asm volatile("cp.async.wait_group 0;" ::: "memory")

__device__ __forceinline__ void split2(float a, float b, uint32_t& h, uint32_t& l) {
    __nv_bfloat162 hb = __floats2bfloat162_rn(a, b);
    float2 hf = __bfloat1622float2(hb);
    __nv_bfloat162 lb = __floats2bfloat162_rn(a - hf.x, b - hf.y);
    h = *reinterpret_cast<uint32_t*>(&hb);
    l = *reinterpret_cast<uint32_t*>(&lb);
}

// ---------------- prep ----------------
__global__ void prep_kernel(const float* __restrict__ W1, const float* __restrict__ W2) {
    int i = blockIdx.x * 256 + threadIdx.x;
    if (i < TT * P1) { g_sum1[i] = 0.f; g_sq1[i] = 0.f; g_sum2[i] = 0.f; g_sq2[i] = 0.f; }
    if (i < P1 * CCAT) {
        int o = i / CCAT, c = i % CCAT;
        float v = W1[i];
        __nv_bfloat16 h = __float2bfloat16_rn(v);
        __nv_bfloat16 l = __float2bfloat16_rn(v - __bfloat162float(h));
        if (c < CIN) { g_W1a_h[c * P1 + o] = h; g_W1a_l[c * P1 + o] = l; }
        else { g_W1b_h[(c - CIN) * P1 + o] = h; g_W1b_l[(c - CIN) * P1 + o] = l; }
    }
    if (i < P2 * P1) {
        int o = i / P1, c = i % P1;
        float v = W2[i];
        __nv_bfloat16 h = __float2bfloat16_rn(v);
        g_W2_h[c * P2 + o] = h;
        g_W2_l[c * P2 + o] = __float2bfloat16_rn(v - __bfloat162float(h));
    }
}

// ---------------- three_nn ----------------
__global__ void knn_kernel(const float* __restrict__ xyzs, const float* __restrict__ oxyzs) {
    __shared__ float sx[NPTS], sy[NPTS], sz[NPTS];
    int f = blockIdx.y;
    const float* p = xyzs + (size_t)f * NPTS * 3;
    for (int i = threadIdx.x; i < NPTS; i += 256) {
        sx[i] = p[3 * i]; sy[i] = p[3 * i + 1]; sz[i] = p[3 * i + 2];
    }
    __syncthreads();
    int m = blockIdx.x * 256 + threadIdx.x;
    const float* q = oxyzs + ((size_t)f * MPTS + m) * 3;
    float qx = q[0], qy = q[1], qz = q[2];
    float b0 = 1e30f, b1 = 1e30f, b2 = 1e30f;
    int   i0 = 0,     i1 = 0,     i2 = 0;
    #pragma unroll 4
    for (int n = 0; n < NPTS; n++) {
        float dx = qx - sx[n], dy = qy - sy[n], dz = qz - sz[n];
        float d = fmaf(dx, dx, fmaf(dy, dy, dz * dz));
        if (d < b2) {
            if (d < b1) {
                b2 = b1; i2 = i1;
                if (d < b0) { b1 = b0; i1 = i0; b0 = d; i0 = n; }
                else        { b1 = d;  i1 = n; }
            } else { b2 = d; i2 = n; }
        }
    }
    float w0 = 1.f / (b0 + EPS_D), w1 = 1.f / (b1 + EPS_D), w2 = 1.f / (b2 + EPS_D);
    float inv = 1.f / (w0 + w1 + w2);
    size_t base = ((size_t)f * MPTS + m) * 3;
    g_idx[base] = i0; g_idx[base + 1] = i1; g_idx[base + 2] = i2;
    g_w[base] = w0 * inv; g_w[base + 1] = w1 * inv; g_w[base + 2] = w2 * inv;
}

// ---------------- HMMA GEMM: C[f][M][256] = A @ W[K][256] ----------------
// CTA 64(M) x 128(N) (N split over blockIdx.x), 8 warps 2x4, warp tile 32x32,
// K chunk 32, double-buffered, B via cp.async (pre-split bf16).
// AMODE 0: A native [k][m] -> ldmatrix.trans ; AMODE 1: A [m][k], fused BN1+ReLU
// FUSE 1: epilogue combine gather(Z)+stats1 -> y1 ; FUSE 2: store + stats2
#define SM_AL_OFF 10240     // A buf stride 5120 (AMODE1 64x40x2; AMODE0 32x72x2=4608)
#define SM_BH_OFF 20480     // B buf stride 8704 (32 x 136 x 2)
#define SM_BL_OFF 37888
#define SM_SC_OFF 55296
#define SM_BI_OFF 56320
#define SMEM_G    57344

template <int K, int AMODE, int FUSE, int MTOT>
__device__ __forceinline__ void gemm_mma(const float* __restrict__ Aall,
                                         const __nv_bfloat16* __restrict__ Bhall,
                                         const __nv_bfloat16* __restrict__ Blall,
                                         float* __restrict__ Call) {
    extern __shared__ char sm[];
    const uint32_t sbase = smem_u32(sm);
    constexpr int NC = K / 32;

    const int tid = threadIdx.x;
    const int l   = tid & 31;
    const int wid = tid >> 5;
    const int wm  = wid >> 2;       // 0..1
    const int wn  = wid & 3;        // 0..3
    const int f   = blockIdx.z, t = f & 3;
    const int bm  = blockIdx.y * 64;
    const int bn0 = blockIdx.x * 128;
    const float* A = Aall + (size_t)f * MTOT * K;
    float*       C = Call + (size_t)f * MTOT * 256;

    float* s_sc = (float*)(sm + SM_SC_OFF);
    float* s_bi = (float*)(sm + SM_BI_OFF);
    if (AMODE == 1) {
        s_sc[tid] = g_a1[t * 256 + tid];
        s_bi[tid] = g_b1[t * 256 + tid];
        __syncthreads();
    }

    // global-load assignments
    const int arow = (AMODE == 1) ? (tid >> 2) : (tid >> 3);
    const int acg  = (AMODE == 1) ? ((tid & 3) * 8) : ((tid & 7) * 8);
    const int bk   = tid >> 3, bnc = (tid & 7) * 16;     // B: 16 bf16 = 32B/thread
    const float* Aptr = (AMODE == 1)
        ? A + (size_t)(bm + arow) * K + acg
        : A + (size_t)arow * MTOT + bm + acg;
    const __nv_bfloat16* Bhp = Bhall + (size_t)bk * 256 + bn0 + bnc;
    const __nv_bfloat16* Blp = Blall + (size_t)bk * 256 + bn0 + bnc;
    const uint32_t bsto = (uint32_t)((bk * 136 + bnc) * 2);

    // ldmatrix lane byte-offsets
    const uint32_t aoff = (AMODE == 1)
        ? (uint32_t)(((l & 15) * 40 + (l >> 4) * 8 + wm * 1280) * 2)
        : (uint32_t)((((l & 7) + ((l >> 4) & 1) * 8) * 72 + ((l >> 3) & 1) * 8 + wm * 32) * 2);
    const uint32_t boff = (uint32_t)((((l & 7) + ((l >> 3) & 1) * 8) * 136 +
                                      (l >> 4) * 8 + wn * 32) * 2);

    float acc[2][4][4];
    #pragma unroll
    for (int i = 0; i < 2; i++)
        #pragma unroll
        for (int j = 0; j < 4; j++)
            #pragma unroll
            for (int k = 0; k < 4; k++) acc[i][j][k] = 0.f;

    float4 ra0, ra1;

    auto issueB = [&](int kc, int buf) {
        const char* bhp = (const char*)(Bhp + (size_t)kc * 32 * 256);
        const char* blp = (const char*)(Blp + (size_t)kc * 32 * 256);
        uint32_t dh = sbase + SM_BH_OFF + buf * 8704 + bsto;
        uint32_t dl = sbase + SM_BL_OFF + buf * 8704 + bsto;
        CP_ASYNC16(dh,      bhp);
        CP_ASYNC16(dh + 16, bhp + 16);
        CP_ASYNC16(dl,      blp);
        CP_ASYNC16(dl + 16, blp + 16);
    };
    auto loadA = [&](int kc) {
        const float* ap = (AMODE == 1) ? (Aptr + kc * 32)
                                       : (Aptr + (size_t)kc * 32 * MTOT);
        ra0 = *(const float4*)ap;
        ra1 = *(const float4*)(ap + 4);
    };
    auto storeA = [&](int buf, int kc) {
        float4 v0 = ra0, v1 = ra1;
        if (AMODE == 1) {
            int cc = kc * 32 + acg;
            v0.x = fmaxf(0.f, fmaf(s_sc[cc + 0], v0.x, s_bi[cc + 0]));
            v0.y = fmaxf(0.f, fmaf(s_sc[cc + 1], v0.y, s_bi[cc + 1]));
            v0.z = fmaxf(0.f, fmaf(s_sc[cc + 2], v0.z, s_bi[cc + 2]));
            v0.w = fmaxf(0.f, fmaf(s_sc[cc + 3], v0.w, s_bi[cc + 3]));
            v1.x = fmaxf(0.f, fmaf(s_sc[cc + 4], v1.x, s_bi[cc + 4]));
            v1.y = fmaxf(0.f, fmaf(s_sc[cc + 5], v1.y, s_bi[cc + 5]));
            v1.z = fmaxf(0.f, fmaf(s_sc[cc + 6], v1.z, s_bi[cc + 6]));
            v1.w = fmaxf(0.f, fmaf(s_sc[cc + 7], v1.w, s_bi[cc + 7]));
        }
        uint32_t h0, l0, h1, l1, h2, l2, h3, l3;
        split2(v0.x, v0.y, h0, l0); split2(v0.z, v0.w, h1, l1);
        split2(v1.x, v1.y, h2, l2); split2(v1.z, v1.w, h3, l3);
        uint32_t ao = (uint32_t)(buf * 5120 +
            ((AMODE == 1) ? (arow * 40 + acg) : (arow * 72 + acg)) * 2);
        *(uint4*)(sm + ao)             = make_uint4(h0, h1, h2, h3);
        *(uint4*)(sm + SM_AL_OFF + ao) = make_uint4(l0, l1, l2, l3);
    };
    auto compute = [&](int buf) {
        #pragma unroll
        for (int ks = 0; ks < 2; ks++) {
            uint32_t ah[2][4], al[2][4];
            #pragma unroll
            for (int mi = 0; mi < 2; mi++) {
                if (AMODE == 1) {
                    uint32_t ad = sbase + buf * 5120 + aoff + mi * 1280 + ks * 32;
                    LDMX4(ah[mi], ad);
                    LDMX4(al[mi], ad + SM_AL_OFF);
                } else {
                    uint32_t ad = sbase + buf * 5120 + aoff + mi * 32 + ks * 2304;
                    LDMX4T(ah[mi], ad);
                    LDMX4T(al[mi], ad + SM_AL_OFF);
                }
            }
            #pragma unroll
            for (int nf = 0; nf < 2; nf++) {
                uint32_t bh[4], bl[4];
                uint32_t bd = sbase + SM_BH_OFF + buf * 8704 + boff + nf * 32 + ks * 4352;
                LDMX4T(bh, bd);
                LDMX4T(bl, bd + 17408);
                const int n0 = nf * 2, n1 = nf * 2 + 1;
                #pragma unroll
                for (int mi = 0; mi < 2; mi++) {
                    MMA_BF16(acc[mi][n0], ah[mi], bh[0], bh[1]);
                    MMA_BF16(acc[mi][n1], ah[mi], bh[2], bh[3]);
                    MMA_BF16(acc[mi][n0], ah[mi], bl[0], bl[1]);
                    MMA_BF16(acc[mi][n1], ah[mi], bl[2], bl[3]);
                    MMA_BF16(acc[mi][n0], al[mi], bh[0], bh[1]);
                    MMA_BF16(acc[mi][n1], al[mi], bh[2], bh[3]);
                }
            }
        }
    };

    issueB(0, 0); CP_COMMIT();
    loadA(0); storeA(0, 0);
    CP_WAIT0();
    __syncthreads();
    for (int kc = 0; kc < NC; kc++) {
        if (kc + 1 < NC) {
            issueB(kc + 1, (kc + 1) & 1); CP_COMMIT();
            loadA(kc + 1);
        }
        compute(kc & 1);
        if (kc + 1 < NC) {
            storeA((kc + 1) & 1, kc + 1);
            CP_WAIT0();
            __syncthreads();
        }
    }

    if (FUSE == 1) {
        // stage acc tile to smem fp32 [64][136], then combine gather(Z)+stats1 -> y1
        __syncthreads();
        float* smf = (float*)sm;
        #pragma unroll
        for (int ni = 0; ni < 4; ni++) {
            int c = wn * 32 + ni * 8 + (l & 3) * 2;
            #pragma unroll
            for (int mi = 0; mi < 2; mi++) {
                int r = wm * 32 + mi * 16 + (l >> 2);
                *(float2*)&smf[r * 136 + c]       = make_float2(acc[mi][ni][0], acc[mi][ni][1]);
                *(float2*)&smf[(r + 8) * 136 + c] = make_float2(acc[mi][ni][2], acc[mi][ni][3]);
            }
        }
        __syncthreads();
        const int oc = tid & 127, half = tid >> 7;
        const int o  = bn0 + oc;
        const float* Z = g_ZT + (size_t)f * NPTS * 256;
        float s = 0.f, q = 0.f;
        #pragma unroll 4
        for (int rr = 0; rr < 32; rr++) {
            int r = half * 32 + rr;
            int m = bm + r;
            size_t ib = ((size_t)f * MPTS + m) * 3;
            int   i0 = g_idx[ib], i1 = g_idx[ib + 1], i2 = g_idx[ib + 2];
            float w0 = g_w[ib],   w1 = g_w[ib + 1],   w2 = g_w[ib + 2];
            float v = smf[r * 136 + oc];
            v = fmaf(w0, Z[(size_t)i0 * 256 + o], v);
            v = fmaf(w1, Z[(size_t)i1 * 256 + o], v);
            v = fmaf(w2, Z[(size_t)i2 * 256 + o], v);
            g_y1[((size_t)f * MPTS + m) * 256 + o] = v;
            s += v; q = fmaf(v, v, q);
        }
        atomicAdd(&g_sum1[t * 256 + o], s);
        atomicAdd(&g_sq1 [t * 256 + o], q);
    } else {
        #pragma unroll
        for (int ni = 0; ni < 4; ni++) {
            int col = bn0 + wn * 32 + ni * 8 + (l & 3) * 2;
            float s0 = 0.f, q0 = 0.f, s1 = 0.f, q1 = 0.f;
            #pragma unroll
            for (int mi = 0; mi < 2; mi++) {
                int row = bm + wm * 32 + mi * 16 + (l >> 2);
                float v0 = acc[mi][ni][0], v1 = acc[mi][ni][1];
                float v2 = acc[mi][ni][2], v3 = acc[mi][ni][3];
                float* cp = C + (size_t)row * 256 + col;
                *(float2*)cp          = make_float2(v0, v1);
                *(float2*)(cp + 2048) = make_float2(v2, v3);   // +8 rows * 256
                if (FUSE == 2) {
                    s0 += v0 + v2; s1 += v1 + v3;
                    q0 += fmaf(v0, v0, v2 * v2);
                    q1 += fmaf(v1, v1, v3 * v3);
                }
            }
            if (FUSE == 2) {
                #pragma unroll
                for (int d = 4; d < 32; d <<= 1) {
                    s0 += __shfl_xor_sync(0xffffffffu, s0, d);
                    s1 += __shfl_xor_sync(0xffffffffu, s1, d);
                    q0 += __shfl_xor_sync(0xffffffffu, q0, d);
                    q1 += __shfl_xor_sync(0xffffffffu, q1, d);
                }
                if (l < 4) {
                    atomicAdd(&g_sum2[t * 256 + col],     s0);
                    atomicAdd(&g_sum2[t * 256 + col + 1], s1);
                    atomicAdd(&g_sq2 [t * 256 + col],     q0);
                    atomicAdd(&g_sq2 [t * 256 + col + 1], q1);
                }
            }
        }
    }
}

__global__ void __launch_bounds__(256, 3) gemmZ_mma(const float* __restrict__ feats) {
    gemm_mma<CIN, 0, 0, NPTS>(feats, g_W1a_h, g_W1a_l, g_ZT);
}
__global__ void __launch_bounds__(256, 3) gemmB_mma(const float* __restrict__ ofeat) {
    gemm_mma<CORIG, 0, 1, MPTS>(ofeat, g_W1b_h, g_W1b_l, g_y1);
}
__global__ void __launch_bounds__(256, 3) gemm2_mma() {
    gemm_mma<P1, 1, 2, MPTS>(g_y1, g_W2_h, g_W2_l, g_y2);
}

// ---------------- finalize BN coefficients ----------------
__global__ void finalize_kernel(int which, const float* __restrict__ gamma,
                                const float* __restrict__ beta) {
    int i = blockIdx.x * 256 + threadIdx.x;
    if (i >= TT * P1) return;
    const float rcnt = 1.0f / (float)(BB * MPTS);
    float sum = (which == 1) ? g_sum1[i] : g_sum2[i];
    float sq  = (which == 1) ? g_sq1[i]  : g_sq2[i];
    float mean = sum * rcnt;
    float var  = fmaf(-mean, mean, sq * rcnt);
    int o = i & 255;
    float a = gamma[o] * rsqrtf(var + EPS_BN);
    float b = fmaf(-mean, a, beta[o]);
    if (which == 1) { g_a1[i] = a; g_b1[i] = b; }
    else            { g_a2[i] = a; g_b2[i] = b; }
}

// ---------------- output: BN2+ReLU + transpose [f][m][o] -> [f][o][m] ----------------
__global__ void output_kernel(float* __restrict__ out) {
    __shared__ float tile[32][33];
    int f = blockIdx.z, t = f & 3;
    int m0 = blockIdx.x * 32, o0 = blockIdx.y * 32;
    int tx = threadIdx.x, ty = threadIdx.y;
    #pragma unroll
    for (int i = ty; i < 32; i += 8) {
        int o = o0 + tx;
        float v = g_y2[((size_t)f * MPTS + m0 + i) * P2 + o];
        tile[i][tx] = fmaxf(0.f, fmaf(g_a2[t * P2 + o], v, g_b2[t * P2 + o]));
    }
    __syncthreads();
    #pragma unroll
    for (int i = ty; i < 32; i += 8)
        out[((size_t)f * P2 + o0 + i) * MPTS + m0 + tx] = tile[tx][i];
}

// ---------------- launch ----------------
extern "C" void kernel_launch(void* const* d_in, const int* in_sizes, int n_in,
                              void* d_out, int out_size) {
    const float* xyzs   = (const float*)d_in[0];
    const float* oxyzs  = (const float*)d_in[1];
    const float* feats  = (const float*)d_in[2];
    const float* ofeat  = (const float*)d_in[3];
    const float* W1     = (const float*)d_in[4];
    const float* gamma1 = (const float*)d_in[5];
    const float* beta1  = (const float*)d_in[6];
    const float* W2     = (const float*)d_in[7];
    const float* gamma2 = (const float*)d_in[8];
    const float* beta2  = (const float*)d_in[9];
    float* out = (float*)d_out;

    (void)cudaFuncSetAttribute(gemmZ_mma, cudaFuncAttributeMaxDynamicSharedMemorySize, SMEM_G);
    (void)cudaFuncSetAttribute(gemmB_mma, cudaFuncAttributeMaxDynamicSharedMemorySize, SMEM_G);
    (void)cudaFuncSetAttribute(gemm2_mma, cudaFuncAttributeMaxDynamicSharedMemorySize, SMEM_G);

    const int xyz_elems = FRAMES * MPTS * 3;
    const int x_elems   = FRAMES * P2 * MPTS;
    float* out_x = out;
    if (out_size >= xyz_elems + x_elems) {
        cudaMemcpyAsync(out, oxyzs, (size_t)xyz_elems * sizeof(float),
                        cudaMemcpyDeviceToDevice, 0);
        out_x = out + xyz_elems;
    }

    prep_kernel<<<384, 256>>>(W1, W2);
    knn_kernel<<<dim3(MPTS / 256, FRAMES), 256>>>(xyzs, oxyzs);

    gemmZ_mma<<<dim3(2, NPTS / 64, FRAMES), 256, SMEM_G>>>(feats);   // Z = feats^T @ W1a
    gemmB_mma<<<dim3(2, MPTS / 64, FRAMES), 256, SMEM_G>>>(ofeat);   // y1 = ofeat^T@W1b + gather(Z); stats1
    finalize_kernel<<<4, 256>>>(1, gamma1, beta1);

    gemm2_mma<<<dim3(2, MPTS / 64, FRAMES), 256, SMEM_G>>>();        // y2 = relu(bn1(y1)) @ W2; stats2
    finalize_kernel<<<4, 256>>>(2, gamma2, beta2);

    output_kernel<<<dim3(MPTS / 32, P2 / 32, FRAMES), dim3(32, 8)>>>(out_x);
}